// round 5
// baseline (speedup 1.0000x reference)
#include <cuda_runtime.h>
#include <cuda_bf16.h>
#include <stdint.h>

#define FXD 64
#define HD 256
#define NTHR 384
#define NW   12

// ---- Precomputed u[b]@W1[128:192] + b1 : [512,256] fp32 ----
__device__ __align__(16) float g_ubb[512 * HD];

__global__ void ubb_kernel(const float* __restrict__ u,
                           const float* __restrict__ W1,
                           const float* __restrict__ b1) {
    __shared__ float us[FXD];
    int b = blockIdx.x, c = threadIdx.x;
    if (c < FXD) us[c] = u[b * FXD + c];
    __syncthreads();
    float acc = b1[c];
#pragma unroll 16
    for (int k = 0; k < FXD; ++k)
        acc = fmaf(us[k], W1[(2 * FXD + k) * HD + c], acc);
    g_ubb[b * HD + c] = acc;
}

__device__ __forceinline__ void split2(float a, float b, uint32_t& hi, uint32_t& lo) {
    __nv_bfloat162 h = __float22bfloat162_rn(make_float2(a, b));  // lo=a, hi=b
    hi = *reinterpret_cast<uint32_t*>(&h);
    float ra = a - __bfloat162float(h.x);
    float rb = b - __bfloat162float(h.y);
    __nv_bfloat162 l = __float22bfloat162_rn(make_float2(ra, rb));
    lo = *reinterpret_cast<uint32_t*>(&l);
}

__device__ __forceinline__ void mma16816(float* c, const uint32_t* a,
                                         uint32_t b0, uint32_t b1) {
    asm volatile(
        "mma.sync.aligned.m16n8k16.row.col.f32.bf16.bf16.f32 "
        "{%0,%1,%2,%3}, {%4,%5,%6,%7}, {%8,%9}, {%0,%1,%2,%3};"
        : "+f"(c[0]), "+f"(c[1]), "+f"(c[2]), "+f"(c[3])
        : "r"(a[0]), "r"(a[1]), "r"(a[2]), "r"(a[3]), "r"(b0), "r"(b1));
}

// SMEM layout (uint4 units):
//   w1s: [8 kstep][32 ntile][32 lane] uint4{hi0,hi1,lo0,lo1}  = 8192 uint4 (128KB)
//   w2s: [16 kstep][8 ntile][32 lane] uint4                   = 4096 uint4 (64KB)
//   b2s: 64 floats
#define W2_OFF  8192
#define B2_OFF  (8192 + 4096)
#define SMEM_SZ ((8192 + 4096) * 16 + 256)

__global__ __launch_bounds__(NTHR, 1)
void edge_mlp_hmma(const float* __restrict__ src,
                   const float* __restrict__ dst,
                   const int* __restrict__ batch,
                   const float* __restrict__ W1,
                   const float* __restrict__ W2,
                   const float* __restrict__ b2,
                   float* __restrict__ out, int E, int B)
{
    extern __shared__ uint4 smem4[];
    uint4* w1s = smem4;
    uint4* w2s = smem4 + W2_OFF;
    float* b2s = (float*)(smem4 + B2_OFF);

    const int tid  = threadIdx.x;
    const int wid  = tid >> 5;
    const int lane = tid & 31;
    const int gg   = lane >> 2;   // group row
    const int tig  = lane & 3;    // thread in group

    // ---- stage W1 as B-fragments, hi/lo bf16 split ----
    for (int i = tid; i < 8 * 32 * 32 * 2; i += NTHR) {
        int p = i & 1, t = (i >> 1) & 31, nt = (i >> 6) & 31, s = (i >> 11);
        int k0 = s * 16 + 2 * (t & 3) + p * 8;
        int n  = nt * 8 + (t >> 2);
        float w0 = W1[k0 * HD + n], w1 = W1[(k0 + 1) * HD + n];
        uint32_t hi, lo; split2(w0, w1, hi, lo);
        uint32_t* cell = (uint32_t*)&w1s[(s * 32 + nt) * 32 + t];
        cell[p] = hi; cell[2 + p] = lo;
    }
    // ---- stage W2 ----
    for (int i = tid; i < 16 * 8 * 32 * 2; i += NTHR) {
        int p = i & 1, t = (i >> 1) & 31, nt = (i >> 6) & 7, s = (i >> 9);
        int k0 = s * 16 + 2 * (t & 3) + p * 8;
        int n  = nt * 8 + (t >> 2);
        float w0 = W2[k0 * 64 + n], w1 = W2[(k0 + 1) * 64 + n];
        uint32_t hi, lo; split2(w0, w1, hi, lo);
        uint32_t* cell = (uint32_t*)&w2s[(s * 8 + nt) * 32 + t];
        cell[p] = hi; cell[2 + p] = lo;
    }
    if (tid < 64) b2s[tid] = b2[tid];
    __syncthreads();

    // ---- warp-autonomous loop over 16-edge groups ----
    const long ngroups = ((long)E + 15) >> 4;
    const long gw0     = (long)blockIdx.x * NW + wid;
    const long gstride = (long)gridDim.x * NW;

    for (long g = gw0; g < ngroups; g += gstride) {
        const long e0 = g * 16 + gg;
        const long e1 = e0 + 8;
        const bool v0 = e0 < (long)E;
        const bool v1 = e1 < (long)E;
        int b0i = v0 ? batch[e0] : 0; b0i = min(max(b0i, 0), B - 1);
        int b1i = v1 ? batch[e1] : 0; b1i = min(max(b1i, 0), B - 1);

        // ---- load A1 fragments (x = [dest|src]) hi/lo ----
        uint32_t Ah[8][4], Al[8][4];
#pragma unroll
        for (int s = 0; s < 8; ++s) {
            const float* xp = (s < 4) ? dst : src;
            const int k = (s & 3) * 16 + 2 * tig;
            float2 z = make_float2(0.f, 0.f);
            float2 p00 = v0 ? *(const float2*)(xp + e0 * 64 + k)     : z;
            float2 p01 = v0 ? *(const float2*)(xp + e0 * 64 + k + 8) : z;
            float2 p10 = v1 ? *(const float2*)(xp + e1 * 64 + k)     : z;
            float2 p11 = v1 ? *(const float2*)(xp + e1 * 64 + k + 8) : z;
            split2(p00.x, p00.y, Ah[s][0], Al[s][0]);
            split2(p10.x, p10.y, Ah[s][1], Al[s][1]);
            split2(p01.x, p01.y, Ah[s][2], Al[s][2]);
            split2(p11.x, p11.y, Ah[s][3], Al[s][3]);
        }

        float C2[32];
#pragma unroll
        for (int i = 0; i < 32; ++i) C2[i] = 0.f;

#pragma unroll 1
        for (int c1 = 0; c1 < 4; ++c1) {
            // ---- GEMM1 chunk: C1[16 x 64] over K=128, 3 passes ----
            float C1[32];
#pragma unroll
            for (int i = 0; i < 32; ++i) C1[i] = 0.f;
#pragma unroll
            for (int s = 0; s < 8; ++s) {
#pragma unroll
                for (int nt = 0; nt < 8; ++nt) {
                    uint4 wv = w1s[(s * 32 + c1 * 8 + nt) * 32 + lane];
                    mma16816(C1 + nt * 4, Ah[s], wv.x, wv.y);   // hi*hi
                    mma16816(C1 + nt * 4, Ah[s], wv.z, wv.w);   // hi*lo
                    mma16816(C1 + nt * 4, Al[s], wv.x, wv.y);   // lo*hi
                }
            }

            // ---- fused epilogue + GEMM2: per q, build A2 frag then MMA ----
            const float* u0 = g_ubb + (size_t)b0i * HD + c1 * 64;
            const float* u1 = g_ubb + (size_t)b1i * HD + c1 * 64;
#pragma unroll
            for (int q = 0; q < 4; ++q) {
                uint32_t A2h[4], A2l[4];
#pragma unroll
                for (int h = 0; h < 2; ++h) {
                    const int nt = 2 * q + h;
                    float2 ua = *(const float2*)(u0 + nt * 8 + 2 * tig);
                    float2 ub = *(const float2*)(u1 + nt * 8 + 2 * tig);
                    float f0 = fmaxf(C1[nt * 4 + 0] + ua.x, 0.f);
                    float f1 = fmaxf(C1[nt * 4 + 1] + ua.y, 0.f);
                    float f2 = fmaxf(C1[nt * 4 + 2] + ub.x, 0.f);
                    float f3 = fmaxf(C1[nt * 4 + 3] + ub.y, 0.f);
                    split2(f0, f1, A2h[2 * h + 0], A2l[2 * h + 0]);
                    split2(f2, f3, A2h[2 * h + 1], A2l[2 * h + 1]);
                }
#pragma unroll
                for (int nt2 = 0; nt2 < 8; ++nt2) {
                    uint4 wv = w2s[((c1 * 4 + q) * 8 + nt2) * 32 + lane];
                    mma16816(C2 + nt2 * 4, A2h, wv.x, wv.y);
                    mma16816(C2 + nt2 * 4, A2h, wv.z, wv.w);
                    mma16816(C2 + nt2 * 4, A2l, wv.x, wv.y);
                }
            }
        }

        // ---- store out = C2 + b2 ----
#pragma unroll
        for (int nt2 = 0; nt2 < 8; ++nt2) {
            const int col = nt2 * 8 + 2 * tig;
            if (v0) {
                float2 o;
                o.x = C2[nt2 * 4 + 0] + b2s[col];
                o.y = C2[nt2 * 4 + 1] + b2s[col + 1];
                *(float2*)(out + e0 * 64 + col) = o;
            }
            if (v1) {
                float2 o;
                o.x = C2[nt2 * 4 + 2] + b2s[col];
                o.y = C2[nt2 * 4 + 3] + b2s[col + 1];
                *(float2*)(out + e1 * 64 + col) = o;
            }
        }
    }
}

extern "C" void kernel_launch(void* const* d_in, const int* in_sizes, int n_in,
                              void* d_out, int out_size) {
    const float* src   = (const float*)d_in[0];
    const float* dest  = (const float*)d_in[1];
    /* d_in[2] = edge_attr, unused by the reference */
    const float* u     = (const float*)d_in[3];
    const int*   batch = (const int*)d_in[4];
    const float* W1    = (const float*)d_in[5];
    const float* b1    = (const float*)d_in[6];
    const float* W2    = (const float*)d_in[7];
    const float* b2    = (const float*)d_in[8];
    float* out = (float*)d_out;

    int E = in_sizes[4];
    int B = in_sizes[3] / FXD;

    ubb_kernel<<<B, 256>>>(u, W1, b1);

    int nsm = 148;
    cudaDeviceGetAttribute(&nsm, cudaDevAttrMultiProcessorCount, 0);
    long ngroups = ((long)E + 15) >> 4;
    long maxcta  = (ngroups + NW - 1) / NW;
    int grid = (int)(maxcta < (long)nsm ? maxcta : (long)nsm);

    cudaFuncSetAttribute(edge_mlp_hmma,
                         cudaFuncAttributeMaxDynamicSharedMemorySize, SMEM_SZ);
    edge_mlp_hmma<<<grid, NTHR, SMEM_SZ>>>(src, dest, batch, W1, W2, b2, out, E, B);
}

// round 6
// speedup vs baseline: 1.0513x; 1.0513x over previous
#include <cuda_runtime.h>
#include <cuda_bf16.h>
#include <stdint.h>

#define FXD 64
#define HD 256
#define NTHR 256
#define NW   8

// ---- Precomputed u[b]@W1[128:192] + b1 : [512,256] fp32 ----
__device__ __align__(16) float g_ubb[512 * HD];

__global__ void ubb_kernel(const float* __restrict__ u,
                           const float* __restrict__ W1,
                           const float* __restrict__ b1) {
    __shared__ float us[FXD];
    int b = blockIdx.x, c = threadIdx.x;
    if (c < FXD) us[c] = u[b * FXD + c];
    __syncthreads();
    float acc = b1[c];
#pragma unroll 16
    for (int k = 0; k < FXD; ++k)
        acc = fmaf(us[k], W1[(2 * FXD + k) * HD + c], acc);
    g_ubb[b * HD + c] = acc;
}

__device__ __forceinline__ void split2(float a, float b, uint32_t& hi, uint32_t& lo) {
    __nv_bfloat162 h = __float22bfloat162_rn(make_float2(a, b));  // lo=a, hi=b
    hi = *reinterpret_cast<uint32_t*>(&h);
    float ra = a - __bfloat162float(h.x);
    float rb = b - __bfloat162float(h.y);
    __nv_bfloat162 l = __float22bfloat162_rn(make_float2(ra, rb));
    lo = *reinterpret_cast<uint32_t*>(&l);
}

__device__ __forceinline__ void mma16816(float* c, const uint32_t* a,
                                         uint32_t b0, uint32_t b1) {
    asm volatile(
        "mma.sync.aligned.m16n8k16.row.col.f32.bf16.bf16.f32 "
        "{%0,%1,%2,%3}, {%4,%5,%6,%7}, {%8,%9}, {%0,%1,%2,%3};"
        : "+f"(c[0]), "+f"(c[1]), "+f"(c[2]), "+f"(c[3])
        : "r"(a[0]), "r"(a[1]), "r"(a[2]), "r"(a[3]), "r"(b0), "r"(b1));
}

// SMEM layout (uint4 units):
//   w1s: [8 kstep][32 ntile][32 lane] uint4{hi0,hi1,lo0,lo1}  = 8192 uint4 (128KB)
//   w2s: [16 kstep][8 ntile][32 lane] uint4                   = 4096 uint4 (64KB)
//   b2s: 64 floats
#define W2_OFF  8192
#define B2_OFF  (8192 + 4096)
#define SMEM_SZ ((8192 + 4096) * 16 + 256)

// epilogue quarter q of chunk cw: relu(C1prev + ubb) -> A2 frags -> 24 GEMM2 MMAs
__device__ __forceinline__ void epi_gemm2(const float* C1p, int cw, int q,
                                          const float2* U0, const float2* U1,
                                          const uint4* w2s, int lane, float* C2) {
    uint32_t A2h[4], A2l[4];
#pragma unroll
    for (int h = 0; h < 2; ++h) {
        const int nt = 2 * q + h;
        float f0 = fmaxf(C1p[nt * 4 + 0] + U0[nt].x, 0.f);
        float f1 = fmaxf(C1p[nt * 4 + 1] + U0[nt].y, 0.f);
        float f2 = fmaxf(C1p[nt * 4 + 2] + U1[nt].x, 0.f);
        float f3 = fmaxf(C1p[nt * 4 + 3] + U1[nt].y, 0.f);
        split2(f0, f1, A2h[2 * h + 0], A2l[2 * h + 0]);
        split2(f2, f3, A2h[2 * h + 1], A2l[2 * h + 1]);
    }
#pragma unroll
    for (int nt2 = 0; nt2 < 8; ++nt2) {
        uint4 wv = w2s[((cw * 4 + q) * 8 + nt2) * 32 + lane];
        mma16816(C2 + nt2 * 4, A2h, wv.x, wv.y);
        mma16816(C2 + nt2 * 4, A2h, wv.z, wv.w);
        mma16816(C2 + nt2 * 4, A2l, wv.x, wv.y);
    }
}

__global__ __launch_bounds__(NTHR, 1)
void edge_mlp_hmma(const float* __restrict__ src,
                   const float* __restrict__ dst,
                   const int* __restrict__ batch,
                   const float* __restrict__ W1,
                   const float* __restrict__ W2,
                   const float* __restrict__ b2,
                   float* __restrict__ out, int E, int B)
{
    extern __shared__ uint4 smem4[];
    uint4* w1s = smem4;
    uint4* w2s = smem4 + W2_OFF;
    float* b2s = (float*)(smem4 + B2_OFF);

    const int tid  = threadIdx.x;
    const int wid  = tid >> 5;
    const int lane = tid & 31;
    const int gg   = lane >> 2;   // group row
    const int tig  = lane & 3;    // thread in group

    // ---- stage W1 as B-fragments, hi/lo bf16 split ----
    for (int i = tid; i < 8 * 32 * 32 * 2; i += NTHR) {
        int p = i & 1, t = (i >> 1) & 31, nt = (i >> 6) & 31, s = (i >> 11);
        int k0 = s * 16 + 2 * (t & 3) + p * 8;
        int n  = nt * 8 + (t >> 2);
        float w0 = W1[k0 * HD + n], w1 = W1[(k0 + 1) * HD + n];
        uint32_t hi, lo; split2(w0, w1, hi, lo);
        uint32_t* cell = (uint32_t*)&w1s[(s * 32 + nt) * 32 + t];
        cell[p] = hi; cell[2 + p] = lo;
    }
    // ---- stage W2 ----
    for (int i = tid; i < 16 * 8 * 32 * 2; i += NTHR) {
        int p = i & 1, t = (i >> 1) & 31, nt = (i >> 6) & 7, s = (i >> 9);
        int k0 = s * 16 + 2 * (t & 3) + p * 8;
        int n  = nt * 8 + (t >> 2);
        float w0 = W2[k0 * 64 + n], w1 = W2[(k0 + 1) * 64 + n];
        uint32_t hi, lo; split2(w0, w1, hi, lo);
        uint32_t* cell = (uint32_t*)&w2s[(s * 8 + nt) * 32 + t];
        cell[p] = hi; cell[2 + p] = lo;
    }
    if (tid < 64) b2s[tid] = b2[tid];
    __syncthreads();

    // ---- warp-autonomous loop over 16-edge groups ----
    const long ngroups = ((long)E + 15) >> 4;
    const long gw0     = (long)blockIdx.x * NW + wid;
    const long gstride = (long)gridDim.x * NW;

    for (long g = gw0; g < ngroups; g += gstride) {
        const long e0 = g * 16 + gg;
        const long e1 = e0 + 8;
        const bool v0 = e0 < (long)E;
        const bool v1 = e1 < (long)E;
        int b0i = v0 ? batch[e0] : 0; b0i = min(max(b0i, 0), B - 1);
        int b1i = v1 ? batch[e1] : 0; b1i = min(max(b1i, 0), B - 1);
        const float* u0base = g_ubb + (size_t)b0i * HD;
        const float* u1base = g_ubb + (size_t)b1i * HD;

        // ---- load A1 fragments (x = [dest|src]) hi/lo ----
        uint32_t Ah[8][4], Al[8][4];
#pragma unroll
        for (int s = 0; s < 8; ++s) {
            const float* xp = (s < 4) ? dst : src;
            const int k = (s & 3) * 16 + 2 * tig;
            float2 z = make_float2(0.f, 0.f);
            float2 p00 = v0 ? *(const float2*)(xp + e0 * 64 + k)     : z;
            float2 p01 = v0 ? *(const float2*)(xp + e0 * 64 + k + 8) : z;
            float2 p10 = v1 ? *(const float2*)(xp + e1 * 64 + k)     : z;
            float2 p11 = v1 ? *(const float2*)(xp + e1 * 64 + k + 8) : z;
            split2(p00.x, p00.y, Ah[s][0], Al[s][0]);
            split2(p10.x, p10.y, Ah[s][1], Al[s][1]);
            split2(p01.x, p01.y, Ah[s][2], Al[s][2]);
            split2(p11.x, p11.y, Ah[s][3], Al[s][3]);
        }

        float C2[32];
#pragma unroll
        for (int i = 0; i < 32; ++i) C2[i] = 0.f;

        float C1a[32], C1b[32];
        float2 U0[8], U1[8];

        // prefetch ubb for chunk 0
#pragma unroll
        for (int nt = 0; nt < 8; ++nt) {
            U0[nt] = *(const float2*)(u0base + nt * 8 + 2 * tig);
            U1[nt] = *(const float2*)(u1base + nt * 8 + 2 * tig);
        }

        // ---- chunk 0 GEMM1 (no interleave) ----
#pragma unroll
        for (int i = 0; i < 32; ++i) C1a[i] = 0.f;
#pragma unroll
        for (int s = 0; s < 8; ++s)
#pragma unroll
            for (int nt = 0; nt < 8; ++nt) {
                uint4 wv = w1s[(s * 32 + nt) * 32 + lane];
                mma16816(C1a + nt * 4, Ah[s], wv.x, wv.y);
                mma16816(C1a + nt * 4, Ah[s], wv.z, wv.w);
                mma16816(C1a + nt * 4, Al[s], wv.x, wv.y);
            }

        // ---- chunks 1..3: GEMM1(c) interleaved with epi+GEMM2(c-1) ----
#pragma unroll
        for (int c1 = 1; c1 < 4; ++c1) {
            float* Ccur  = (c1 & 1) ? C1b : C1a;
            float* Cprev = (c1 & 1) ? C1a : C1b;
#pragma unroll
            for (int i = 0; i < 32; ++i) Ccur[i] = 0.f;
#pragma unroll
            for (int s = 0; s < 8; ++s) {
#pragma unroll
                for (int nt = 0; nt < 8; ++nt) {
                    uint4 wv = w1s[(s * 32 + c1 * 8 + nt) * 32 + lane];
                    mma16816(Ccur + nt * 4, Ah[s], wv.x, wv.y);
                    mma16816(Ccur + nt * 4, Ah[s], wv.z, wv.w);
                    mma16816(Ccur + nt * 4, Al[s], wv.x, wv.y);
                }
                if (s & 1)
                    epi_gemm2(Cprev, c1 - 1, s >> 1, U0, U1, w2s, lane, C2);
            }
            // reload ubb prefetch for this chunk (used during next iteration / tail)
#pragma unroll
            for (int nt = 0; nt < 8; ++nt) {
                U0[nt] = *(const float2*)(u0base + c1 * 64 + nt * 8 + 2 * tig);
                U1[nt] = *(const float2*)(u1base + c1 * 64 + nt * 8 + 2 * tig);
            }
        }

        // ---- tail: epilogue + GEMM2 for chunk 3 (lives in C1b) ----
#pragma unroll
        for (int q = 0; q < 4; ++q)
            epi_gemm2(C1b, 3, q, U0, U1, w2s, lane, C2);

        // ---- store out = C2 + b2 ----
#pragma unroll
        for (int nt2 = 0; nt2 < 8; ++nt2) {
            const int col = nt2 * 8 + 2 * tig;
            if (v0) {
                float2 o;
                o.x = C2[nt2 * 4 + 0] + b2s[col];
                o.y = C2[nt2 * 4 + 1] + b2s[col + 1];
                *(float2*)(out + e0 * 64 + col) = o;
            }
            if (v1) {
                float2 o;
                o.x = C2[nt2 * 4 + 2] + b2s[col];
                o.y = C2[nt2 * 4 + 3] + b2s[col + 1];
                *(float2*)(out + e1 * 64 + col) = o;
            }
        }
    }
}

extern "C" void kernel_launch(void* const* d_in, const int* in_sizes, int n_in,
                              void* d_out, int out_size) {
    const float* src   = (const float*)d_in[0];
    const float* dest  = (const float*)d_in[1];
    /* d_in[2] = edge_attr, unused by the reference */
    const float* u     = (const float*)d_in[3];
    const int*   batch = (const int*)d_in[4];
    const float* W1    = (const float*)d_in[5];
    const float* b1    = (const float*)d_in[6];
    const float* W2    = (const float*)d_in[7];
    const float* b2    = (const float*)d_in[8];
    float* out = (float*)d_out;

    int E = in_sizes[4];
    int B = in_sizes[3] / FXD;

    ubb_kernel<<<B, 256>>>(u, W1, b1);

    int nsm = 148;
    cudaDeviceGetAttribute(&nsm, cudaDevAttrMultiProcessorCount, 0);
    long ngroups = ((long)E + 15) >> 4;
    long maxcta  = (ngroups + NW - 1) / NW;
    int grid = (int)(maxcta < (long)nsm ? maxcta : (long)nsm);

    cudaFuncSetAttribute(edge_mlp_hmma,
                         cudaFuncAttributeMaxDynamicSharedMemorySize, SMEM_SZ);
    edge_mlp_hmma<<<grid, NTHR, SMEM_SZ>>>(src, dest, batch, W1, W2, b2, out, E, B);
}

// round 7
// speedup vs baseline: 1.3937x; 1.3257x over previous
#include <cuda_runtime.h>
#include <cuda_fp16.h>
#include <stdint.h>

#define FXD 64
#define HD 256
#define NTHR 256
#define NW   8

// ---- Precomputed u[b]@W1[128:192] + b1 : [512,256] fp32 ----
__device__ __align__(16) float g_ubb[512 * HD];

__global__ void ubb_kernel(const float* __restrict__ u,
                           const float* __restrict__ W1,
                           const float* __restrict__ b1) {
    __shared__ float us[FXD];
    int b = blockIdx.x, c = threadIdx.x;
    if (c < FXD) us[c] = u[b * FXD + c];
    __syncthreads();
    float acc = b1[c];
#pragma unroll 16
    for (int k = 0; k < FXD; ++k)
        acc = fmaf(us[k], W1[(2 * FXD + k) * HD + c], acc);
    g_ubb[b * HD + c] = acc;
}

__device__ __forceinline__ uint32_t packf16(float a, float b) {
    __half2 h = __floats2half2_rn(a, b);
    return *reinterpret_cast<uint32_t*>(&h);
}
__device__ __forceinline__ void splitf16(float a, float b, uint32_t& hi, uint32_t& lo) {
    __half2 h = __floats2half2_rn(a, b);
    hi = *reinterpret_cast<uint32_t*>(&h);
    float ra = a - __half2float(__low2half(h));
    float rb = b - __half2float(__high2half(h));
    __half2 l = __floats2half2_rn(ra, rb);
    lo = *reinterpret_cast<uint32_t*>(&l);
}

__device__ __forceinline__ void mma16816(float* c, const uint32_t* a,
                                         uint32_t b0, uint32_t b1) {
    asm volatile(
        "mma.sync.aligned.m16n8k16.row.col.f32.f16.f16.f32 "
        "{%0,%1,%2,%3}, {%4,%5,%6,%7}, {%8,%9}, {%0,%1,%2,%3};"
        : "+f"(c[0]), "+f"(c[1]), "+f"(c[2]), "+f"(c[3])
        : "r"(a[0]), "r"(a[1]), "r"(a[2]), "r"(a[3]), "r"(b0), "r"(b1));
}

// SMEM layout (uint4 units):
//   w1s: [8 kstep][32 ntile][32 lane] uint4{Wh_p0, Wh_p1, Wl_p0, Wl_p1}
//   w2s: [16 kstep][8 ntile][32 lane] uint4
#define W2_OFF  8192
#define B2_OFF  (8192 + 4096)
#define SMEM_SZ ((8192 + 4096) * 16 + 256)

// epilogue quarter q of chunk cw: relu(C1prev + ubb) -> fp16 A2 -> 16 GEMM2 MMAs
__device__ __forceinline__ void epi_gemm2(const float* C1p, int cw, int q,
                                          const float2* U0, const float2* U1,
                                          const uint4* w2s, int lane, float* C2) {
    uint32_t A2[4];
#pragma unroll
    for (int h = 0; h < 2; ++h) {
        const int nt = 2 * q + h;
        float f0 = fmaxf(C1p[nt * 4 + 0] + U0[nt].x, 0.f);
        float f1 = fmaxf(C1p[nt * 4 + 1] + U0[nt].y, 0.f);
        float f2 = fmaxf(C1p[nt * 4 + 2] + U1[nt].x, 0.f);
        float f3 = fmaxf(C1p[nt * 4 + 3] + U1[nt].y, 0.f);
        A2[2 * h + 0] = packf16(f0, f1);
        A2[2 * h + 1] = packf16(f2, f3);
    }
#pragma unroll
    for (int nt2 = 0; nt2 < 8; ++nt2) {
        uint4 wv = w2s[((cw * 4 + q) * 8 + nt2) * 32 + lane];
        mma16816(C2 + nt2 * 4, A2, wv.x, wv.y);
        mma16816(C2 + nt2 * 4, A2, wv.z, wv.w);
    }
}

__global__ __launch_bounds__(NTHR, 1)
void edge_mlp_hmma(const float* __restrict__ src,
                   const float* __restrict__ dst,
                   const int* __restrict__ batch,
                   const float* __restrict__ W1,
                   const float* __restrict__ W2,
                   const float* __restrict__ b2,
                   float* __restrict__ out, int E, int B)
{
    extern __shared__ uint4 smem4[];
    uint4* w1s = smem4;
    uint4* w2s = smem4 + W2_OFF;
    float* b2s = (float*)(smem4 + B2_OFF);

    const int tid  = threadIdx.x;
    const int wid  = tid >> 5;
    const int lane = tid & 31;
    const int gg   = lane >> 2;   // group row
    const int tig  = lane & 3;    // thread in group

    // ---- stage W1 as B-fragments, fp16 hi/lo split of the weight ----
    for (int i = tid; i < 8 * 32 * 32 * 2; i += NTHR) {
        int p = i & 1, t = (i >> 1) & 31, nt = (i >> 6) & 31, s = (i >> 11);
        int k0 = s * 16 + 2 * (t & 3) + p * 8;
        int n  = nt * 8 + (t >> 2);
        float w0 = W1[k0 * HD + n], w1 = W1[(k0 + 1) * HD + n];
        uint32_t hi, lo; splitf16(w0, w1, hi, lo);
        uint32_t* cell = (uint32_t*)&w1s[(s * 32 + nt) * 32 + t];
        cell[p] = hi; cell[2 + p] = lo;
    }
    // ---- stage W2 ----
    for (int i = tid; i < 16 * 8 * 32 * 2; i += NTHR) {
        int p = i & 1, t = (i >> 1) & 31, nt = (i >> 6) & 7, s = (i >> 9);
        int k0 = s * 16 + 2 * (t & 3) + p * 8;
        int n  = nt * 8 + (t >> 2);
        float w0 = W2[k0 * 64 + n], w1 = W2[(k0 + 1) * 64 + n];
        uint32_t hi, lo; splitf16(w0, w1, hi, lo);
        uint32_t* cell = (uint32_t*)&w2s[(s * 8 + nt) * 32 + t];
        cell[p] = hi; cell[2 + p] = lo;
    }
    if (tid < 64) b2s[tid] = b2[tid];
    __syncthreads();

    // ---- warp-autonomous loop over 16-edge groups ----
    const long ngroups = ((long)E + 15) >> 4;
    const long gw0     = (long)blockIdx.x * NW + wid;
    const long gstride = (long)gridDim.x * NW;

    for (long g = gw0; g < ngroups; g += gstride) {
        const long e0 = g * 16 + gg;
        const long e1 = e0 + 8;
        const bool v0 = e0 < (long)E;
        const bool v1 = e1 < (long)E;
        int b0i = v0 ? batch[e0] : 0; b0i = min(max(b0i, 0), B - 1);
        int b1i = v1 ? batch[e1] : 0; b1i = min(max(b1i, 0), B - 1);
        const float* u0base = g_ubb + (size_t)b0i * HD;
        const float* u1base = g_ubb + (size_t)b1i * HD;

        // ---- load A1 fragments (x = [dest|src]) fp16 ----
        uint32_t Ah[8][4];
#pragma unroll
        for (int s = 0; s < 8; ++s) {
            const float* xp = (s < 4) ? dst : src;
            const int k = (s & 3) * 16 + 2 * tig;
            float2 z = make_float2(0.f, 0.f);
            float2 p00 = v0 ? *(const float2*)(xp + e0 * 64 + k)     : z;
            float2 p01 = v0 ? *(const float2*)(xp + e0 * 64 + k + 8) : z;
            float2 p10 = v1 ? *(const float2*)(xp + e1 * 64 + k)     : z;
            float2 p11 = v1 ? *(const float2*)(xp + e1 * 64 + k + 8) : z;
            Ah[s][0] = packf16(p00.x, p00.y);
            Ah[s][1] = packf16(p10.x, p10.y);
            Ah[s][2] = packf16(p01.x, p01.y);
            Ah[s][3] = packf16(p11.x, p11.y);
        }

        float C2[32];
#pragma unroll
        for (int i = 0; i < 32; ++i) C2[i] = 0.f;

        float C1a[32], C1b[32];
        float2 U0[8], U1[8];

        // prefetch ubb for chunk 0
#pragma unroll
        for (int nt = 0; nt < 8; ++nt) {
            U0[nt] = *(const float2*)(u0base + nt * 8 + 2 * tig);
            U1[nt] = *(const float2*)(u1base + nt * 8 + 2 * tig);
        }

        // ---- chunk 0 GEMM1 (no interleave) ----
#pragma unroll
        for (int i = 0; i < 32; ++i) C1a[i] = 0.f;
#pragma unroll
        for (int s = 0; s < 8; ++s)
#pragma unroll
            for (int nt = 0; nt < 8; ++nt) {
                uint4 wv = w1s[(s * 32 + nt) * 32 + lane];
                mma16816(C1a + nt * 4, Ah[s], wv.x, wv.y);
                mma16816(C1a + nt * 4, Ah[s], wv.z, wv.w);
            }

        // ---- chunks 1..3: GEMM1(c) interleaved with epi+GEMM2(c-1) ----
#pragma unroll
        for (int c1 = 1; c1 < 4; ++c1) {
            float* Ccur  = (c1 & 1) ? C1b : C1a;
            float* Cprev = (c1 & 1) ? C1a : C1b;
#pragma unroll
            for (int i = 0; i < 32; ++i) Ccur[i] = 0.f;
#pragma unroll
            for (int s = 0; s < 8; ++s) {
#pragma unroll
                for (int nt = 0; nt < 8; ++nt) {
                    uint4 wv = w1s[(s * 32 + c1 * 8 + nt) * 32 + lane];
                    mma16816(Ccur + nt * 4, Ah[s], wv.x, wv.y);
                    mma16816(Ccur + nt * 4, Ah[s], wv.z, wv.w);
                }
                if (s & 1)
                    epi_gemm2(Cprev, c1 - 1, s >> 1, U0, U1, w2s, lane, C2);
            }
            // reload ubb prefetch for this chunk
#pragma unroll
            for (int nt = 0; nt < 8; ++nt) {
                U0[nt] = *(const float2*)(u0base + c1 * 64 + nt * 8 + 2 * tig);
                U1[nt] = *(const float2*)(u1base + c1 * 64 + nt * 8 + 2 * tig);
            }
        }

        // ---- tail: epilogue + GEMM2 for chunk 3 (lives in C1b) ----
#pragma unroll
        for (int q = 0; q < 4; ++q)
            epi_gemm2(C1b, 3, q, U0, U1, w2s, lane, C2);

        // ---- store out = C2 + b2 ----
#pragma unroll
        for (int nt2 = 0; nt2 < 8; ++nt2) {
            const int col = nt2 * 8 + 2 * tig;
            if (v0) {
                float2 o;
                o.x = C2[nt2 * 4 + 0] + b2s[col];
                o.y = C2[nt2 * 4 + 1] + b2s[col + 1];
                *(float2*)(out + e0 * 64 + col) = o;
            }
            if (v1) {
                float2 o;
                o.x = C2[nt2 * 4 + 2] + b2s[col];
                o.y = C2[nt2 * 4 + 3] + b2s[col + 1];
                *(float2*)(out + e1 * 64 + col) = o;
            }
        }
    }
}

extern "C" void kernel_launch(void* const* d_in, const int* in_sizes, int n_in,
                              void* d_out, int out_size) {
    const float* src   = (const float*)d_in[0];
    const float* dest  = (const float*)d_in[1];
    /* d_in[2] = edge_attr, unused by the reference */
    const float* u     = (const float*)d_in[3];
    const int*   batch = (const int*)d_in[4];
    const float* W1    = (const float*)d_in[5];
    const float* b1    = (const float*)d_in[6];
    const float* W2    = (const float*)d_in[7];
    const float* b2    = (const float*)d_in[8];
    float* out = (float*)d_out;

    int E = in_sizes[4];
    int B = in_sizes[3] / FXD;

    ubb_kernel<<<B, 256>>>(u, W1, b1);

    int nsm = 148;
    cudaDeviceGetAttribute(&nsm, cudaDevAttrMultiProcessorCount, 0);
    long ngroups = ((long)E + 15) >> 4;
    long maxcta  = (ngroups + NW - 1) / NW;
    int grid = (int)(maxcta < (long)nsm ? maxcta : (long)nsm);

    cudaFuncSetAttribute(edge_mlp_hmma,
                         cudaFuncAttributeMaxDynamicSharedMemorySize, SMEM_SZ);
    edge_mlp_hmma<<<grid, NTHR, SMEM_SZ>>>(src, dest, batch, W1, W2, b2, out, E, B);
}

// round 8
// speedup vs baseline: 2.0250x; 1.4530x over previous
#include <cuda_runtime.h>
#include <cuda_fp16.h>
#include <stdint.h>

#define FXD 64
#define HD 256
#define NTHR 256
#define NW   8

// ---- Precomputed u[b]@W1[128:192] + b1 : [512,256] fp32 ----
__device__ __align__(16) float g_ubb[512 * HD];

__global__ void ubb_kernel(const float* __restrict__ u,
                           const float* __restrict__ W1,
                           const float* __restrict__ b1) {
    __shared__ float us[FXD];
    int b = blockIdx.x, c = threadIdx.x;
    if (c < FXD) us[c] = u[b * FXD + c];
    __syncthreads();
    float acc = b1[c];
#pragma unroll 16
    for (int k = 0; k < FXD; ++k)
        acc = fmaf(us[k], W1[(2 * FXD + k) * HD + c], acc);
    g_ubb[b * HD + c] = acc;
}

__device__ __forceinline__ uint32_t packf16(float a, float b) {
    __half2 h = __floats2half2_rn(a, b);
    return *reinterpret_cast<uint32_t*>(&h);
}

__device__ __forceinline__ void mma16816(float* c, const uint32_t* a,
                                         uint32_t b0, uint32_t b1) {
    asm volatile(
        "mma.sync.aligned.m16n8k16.row.col.f32.f16.f16.f32 "
        "{%0,%1,%2,%3}, {%4,%5,%6,%7}, {%8,%9}, {%0,%1,%2,%3};"
        : "+f"(c[0]), "+f"(c[1]), "+f"(c[2]), "+f"(c[3])
        : "r"(a[0]), "r"(a[1]), "r"(a[2]), "r"(a[3]), "r"(b0), "r"(b1));
}

// SMEM (uint4 units): each uint4 = B-frags for TWO adjacent n-tiles (fp16, no split)
//   w1s: [8 kstep][16 ntpair][32 lane]  = 4096 uint4 (64KB)
//   w2s: [16 kstep][4 ntpair][32 lane]  = 2048 uint4 (32KB)
#define W2_OFF  4096
#define B2_OFF  (4096 + 2048)
#define SMEM_SZ ((4096 + 2048) * 16 + 256)

__global__ __launch_bounds__(NTHR, 1)
void edge_mlp_hmma(const float* __restrict__ src,
                   const float* __restrict__ dst,
                   const int* __restrict__ batch,
                   const float* __restrict__ W1,
                   const float* __restrict__ W2,
                   const float* __restrict__ b2,
                   float* __restrict__ out, int E, int B)
{
    extern __shared__ uint4 smem4[];
    uint4* w1s = smem4;
    uint4* w2s = smem4 + W2_OFF;
    float* b2s = (float*)(smem4 + B2_OFF);

    const int tid  = threadIdx.x;
    const int wid  = tid >> 5;
    const int lane = tid & 31;
    const int gg   = lane >> 2;   // group row
    const int tig  = lane & 3;    // thread in group

    // ---- stage W1 fp16 B-fragments: cell(s,ntp,lane) = {nt0p0,nt0p1,nt1p0,nt1p1} ----
    for (int i = tid; i < 8 * 16 * 32 * 4; i += NTHR) {
        int c = i & 3, t = (i >> 2) & 31, ntp = (i >> 7) & 15, s = i >> 11;
        int h = c >> 1, p = c & 1;
        int n  = (2 * ntp + h) * 8 + (t >> 2);
        int k0 = s * 16 + 2 * (t & 3) + p * 8;
        ((uint32_t*)&w1s[(s * 16 + ntp) * 32 + t])[c] =
            packf16(W1[k0 * HD + n], W1[(k0 + 1) * HD + n]);
    }
    // ---- stage W2 ----
    for (int i = tid; i < 16 * 4 * 32 * 4; i += NTHR) {
        int c = i & 3, t = (i >> 2) & 31, ntp = (i >> 7) & 3, s = i >> 9;
        int h = c >> 1, p = c & 1;
        int n  = (2 * ntp + h) * 8 + (t >> 2);
        int k0 = s * 16 + 2 * (t & 3) + p * 8;
        ((uint32_t*)&w2s[(s * 4 + ntp) * 32 + t])[c] =
            packf16(W2[k0 * 64 + n], W2[(k0 + 1) * 64 + n]);
    }
    if (tid < 64) b2s[tid] = b2[tid];
    __syncthreads();

    // ---- warp-autonomous loop over 16-edge groups ----
    const long ngroups = ((long)E + 15) >> 4;
    const long gw0     = (long)blockIdx.x * NW + wid;
    const long gstride = (long)gridDim.x * NW;

    for (long g = gw0; g < ngroups; g += gstride) {
        const long e0 = g * 16 + gg;
        const long e1 = e0 + 8;
        const bool v0 = e0 < (long)E;
        const bool v1 = e1 < (long)E;
        int b0i = v0 ? batch[e0] : 0; b0i = min(max(b0i, 0), B - 1);
        int b1i = v1 ? batch[e1] : 0; b1i = min(max(b1i, 0), B - 1);
        const float* u0base = g_ubb + (size_t)b0i * HD;
        const float* u1base = g_ubb + (size_t)b1i * HD;

        // ---- load A1 fragments (x = [dest|src]) fp16 ----
        uint32_t Ah[8][4];
#pragma unroll
        for (int s = 0; s < 8; ++s) {
            const float* xp = (s < 4) ? dst : src;
            const int k = (s & 3) * 16 + 2 * tig;
            float2 z = make_float2(0.f, 0.f);
            float2 p00 = v0 ? *(const float2*)(xp + e0 * 64 + k)     : z;
            float2 p01 = v0 ? *(const float2*)(xp + e0 * 64 + k + 8) : z;
            float2 p10 = v1 ? *(const float2*)(xp + e1 * 64 + k)     : z;
            float2 p11 = v1 ? *(const float2*)(xp + e1 * 64 + k + 8) : z;
            Ah[s][0] = packf16(p00.x, p00.y);
            Ah[s][1] = packf16(p10.x, p10.y);
            Ah[s][2] = packf16(p01.x, p01.y);
            Ah[s][3] = packf16(p11.x, p11.y);
        }

        float C2[32];
#pragma unroll
        for (int i = 0; i < 32; ++i) C2[i] = 0.f;

#pragma unroll
        for (int c1 = 0; c1 < 4; ++c1) {
            // prefetch ubb slices for this chunk
            float2 U0[8], U1[8];
#pragma unroll
            for (int nt = 0; nt < 8; ++nt) {
                U0[nt] = *(const float2*)(u0base + c1 * 64 + nt * 8 + 2 * tig);
                U1[nt] = *(const float2*)(u1base + c1 * 64 + nt * 8 + 2 * tig);
            }

            // ---- GEMM1 chunk: C1[16 x 64], K=128, single pass ----
            float C1[32];
#pragma unroll
            for (int i = 0; i < 32; ++i) C1[i] = 0.f;
#pragma unroll
            for (int s = 0; s < 8; ++s) {
#pragma unroll
                for (int ntp = 0; ntp < 4; ++ntp) {
                    uint4 wv = w1s[(s * 16 + c1 * 4 + ntp) * 32 + lane];
                    mma16816(C1 + (2 * ntp + 0) * 4, Ah[s], wv.x, wv.y);
                    mma16816(C1 + (2 * ntp + 1) * 4, Ah[s], wv.z, wv.w);
                }
            }

            // ---- epilogue + GEMM2 partial ----
#pragma unroll
            for (int q = 0; q < 4; ++q) {
                uint32_t A2[4];
#pragma unroll
                for (int h = 0; h < 2; ++h) {
                    const int nt = 2 * q + h;
                    float f0 = fmaxf(C1[nt * 4 + 0] + U0[nt].x, 0.f);
                    float f1 = fmaxf(C1[nt * 4 + 1] + U0[nt].y, 0.f);
                    float f2 = fmaxf(C1[nt * 4 + 2] + U1[nt].x, 0.f);
                    float f3 = fmaxf(C1[nt * 4 + 3] + U1[nt].y, 0.f);
                    A2[2 * h + 0] = packf16(f0, f1);
                    A2[2 * h + 1] = packf16(f2, f3);
                }
#pragma unroll
                for (int ntp = 0; ntp < 4; ++ntp) {
                    uint4 wv = w2s[((c1 * 4 + q) * 4 + ntp) * 32 + lane];
                    mma16816(C2 + (2 * ntp + 0) * 4, A2, wv.x, wv.y);
                    mma16816(C2 + (2 * ntp + 1) * 4, A2, wv.z, wv.w);
                }
            }
        }

        // ---- store out = C2 + b2 ----
#pragma unroll
        for (int nt2 = 0; nt2 < 8; ++nt2) {
            const int col = nt2 * 8 + 2 * tig;
            if (v0) {
                float2 o;
                o.x = C2[nt2 * 4 + 0] + b2s[col];
                o.y = C2[nt2 * 4 + 1] + b2s[col + 1];
                *(float2*)(out + e0 * 64 + col) = o;
            }
            if (v1) {
                float2 o;
                o.x = C2[nt2 * 4 + 2] + b2s[col];
                o.y = C2[nt2 * 4 + 3] + b2s[col + 1];
                *(float2*)(out + e1 * 64 + col) = o;
            }
        }
    }
}

extern "C" void kernel_launch(void* const* d_in, const int* in_sizes, int n_in,
                              void* d_out, int out_size) {
    const float* src   = (const float*)d_in[0];
    const float* dest  = (const float*)d_in[1];
    /* d_in[2] = edge_attr, unused by the reference */
    const float* u     = (const float*)d_in[3];
    const int*   batch = (const int*)d_in[4];
    const float* W1    = (const float*)d_in[5];
    const float* b1    = (const float*)d_in[6];
    const float* W2    = (const float*)d_in[7];
    const float* b2    = (const float*)d_in[8];
    float* out = (float*)d_out;

    int E = in_sizes[4];
    int B = in_sizes[3] / FXD;

    ubb_kernel<<<B, 256>>>(u, W1, b1);

    int nsm = 148;
    cudaDeviceGetAttribute(&nsm, cudaDevAttrMultiProcessorCount, 0);
    long ngroups = ((long)E + 15) >> 4;
    long maxcta  = (ngroups + NW - 1) / NW;
    int grid = (int)(maxcta < (long)nsm ? maxcta : (long)nsm);

    cudaFuncSetAttribute(edge_mlp_hmma,
                         cudaFuncAttributeMaxDynamicSharedMemorySize, SMEM_SZ);
    edge_mlp_hmma<<<grid, NTHR, SMEM_SZ>>>(src, dest, batch, W1, W2, b2, out, E, B);
}

// round 9
// speedup vs baseline: 2.2491x; 1.1106x over previous
#include <cuda_runtime.h>
#include <cuda_fp16.h>
#include <stdint.h>

#define FXD 64
#define HD 256
#define NTHR 256
#define NW   8

// ---- Precomputed u[b]@W1[128:192] + b1 : [512,256] fp32 ----
__device__ __align__(16) float g_ubb[512 * HD];

__global__ void ubb_kernel(const float* __restrict__ u,
                           const float* __restrict__ W1,
                           const float* __restrict__ b1) {
    __shared__ float us[FXD];
    int b = blockIdx.x, c = threadIdx.x;
    if (c < FXD) us[c] = u[b * FXD + c];
    __syncthreads();
    float acc = b1[c];
#pragma unroll 16
    for (int k = 0; k < FXD; ++k)
        acc = fmaf(us[k], W1[(2 * FXD + k) * HD + c], acc);
    g_ubb[b * HD + c] = acc;
}

__device__ __forceinline__ uint32_t packf16(float a, float b) {
    __half2 h = __floats2half2_rn(a, b);
    return *reinterpret_cast<uint32_t*>(&h);
}

__device__ __forceinline__ void mma16816(float* c, const uint32_t* a,
                                         uint32_t b0, uint32_t b1) {
    asm volatile(
        "mma.sync.aligned.m16n8k16.row.col.f32.f16.f16.f32 "
        "{%0,%1,%2,%3}, {%4,%5,%6,%7}, {%8,%9}, {%0,%1,%2,%3};"
        : "+f"(c[0]), "+f"(c[1]), "+f"(c[2]), "+f"(c[3])
        : "r"(a[0]), "r"(a[1]), "r"(a[2]), "r"(a[3]), "r"(b0), "r"(b1));
}

// SMEM (uint4 units): each uint4 = B-frags for TWO adjacent n-tiles (fp16)
//   w1s: [8 kstep][16 ntpair][32 lane]  = 4096 uint4 (64KB)
//   w2s: [16 kstep][4 ntpair][32 lane]  = 2048 uint4 (32KB)
#define W2_OFF  4096
#define B2_OFF  (4096 + 2048)
#define SMEM_SZ ((4096 + 2048) * 16 + 256)

__global__ __launch_bounds__(NTHR, 1)
void edge_mlp_hmma(const float* __restrict__ src,
                   const float* __restrict__ dst,
                   const int* __restrict__ batch,
                   const float* __restrict__ W1,
                   const float* __restrict__ W2,
                   const float* __restrict__ b2,
                   float* __restrict__ out, int E, int B)
{
    extern __shared__ uint4 smem4[];
    uint4* w1s = smem4;
    uint4* w2s = smem4 + W2_OFF;
    float* b2s = (float*)(smem4 + B2_OFF);

    const int tid  = threadIdx.x;
    const int wid  = tid >> 5;
    const int lane = tid & 31;
    const int gg   = lane >> 2;   // group row
    const int tig  = lane & 3;    // thread in group

    // ---- stage W1 fp16 B-fragments ----
    for (int i = tid; i < 8 * 16 * 32 * 4; i += NTHR) {
        int c = i & 3, t = (i >> 2) & 31, ntp = (i >> 7) & 15, s = i >> 11;
        int h = c >> 1, p = c & 1;
        int n  = (2 * ntp + h) * 8 + (t >> 2);
        int k0 = s * 16 + 2 * (t & 3) + p * 8;
        ((uint32_t*)&w1s[(s * 16 + ntp) * 32 + t])[c] =
            packf16(W1[k0 * HD + n], W1[(k0 + 1) * HD + n]);
    }
    // ---- stage W2 ----
    for (int i = tid; i < 16 * 4 * 32 * 4; i += NTHR) {
        int c = i & 3, t = (i >> 2) & 31, ntp = (i >> 7) & 3, s = i >> 9;
        int h = c >> 1, p = c & 1;
        int n  = (2 * ntp + h) * 8 + (t >> 2);
        int k0 = s * 16 + 2 * (t & 3) + p * 8;
        ((uint32_t*)&w2s[(s * 4 + ntp) * 32 + t])[c] =
            packf16(W2[k0 * 64 + n], W2[(k0 + 1) * 64 + n]);
    }
    if (tid < 64) b2s[tid] = b2[tid];
    __syncthreads();

    // ---- warp-autonomous loop over 32-edge groups ----
    const long ngroups = ((long)E + 31) >> 5;
    const long gw0     = (long)blockIdx.x * NW + wid;
    const long gstride = (long)gridDim.x * NW;

    for (long g = gw0; g < ngroups; g += gstride) {
        long ee[4];
        bool vv[4];
        const float* ub[4];
#pragma unroll
        for (int j = 0; j < 4; ++j) {
            ee[j] = g * 32 + gg + 8 * j;
            vv[j] = ee[j] < (long)E;
            int bi = vv[j] ? batch[ee[j]] : 0;
            bi = min(max(bi, 0), B - 1);
            ub[j] = g_ubb + (size_t)bi * HD;
        }

        // ---- load A1 fragments: Ah[s][0..3] = mtile0 (rows 0-15), [4..7] = mtile1 ----
        uint32_t Ah[8][8];
#pragma unroll
        for (int s = 0; s < 8; ++s) {
            const float* xp = (s < 4) ? dst : src;
            const int k = (s & 3) * 16 + 2 * tig;
            float2 z = make_float2(0.f, 0.f);
#pragma unroll
            for (int m = 0; m < 2; ++m) {
                long ea = ee[2 * m], eb = ee[2 * m + 1];
                float2 pa0 = vv[2 * m]     ? *(const float2*)(xp + ea * 64 + k)     : z;
                float2 pa1 = vv[2 * m]     ? *(const float2*)(xp + ea * 64 + k + 8) : z;
                float2 pb0 = vv[2 * m + 1] ? *(const float2*)(xp + eb * 64 + k)     : z;
                float2 pb1 = vv[2 * m + 1] ? *(const float2*)(xp + eb * 64 + k + 8) : z;
                Ah[s][4 * m + 0] = packf16(pa0.x, pa0.y);
                Ah[s][4 * m + 1] = packf16(pb0.x, pb0.y);
                Ah[s][4 * m + 2] = packf16(pa1.x, pa1.y);
                Ah[s][4 * m + 3] = packf16(pb1.x, pb1.y);
            }
        }

        // C2[(nt2*2 + m)*4 + r] : 32 rows x 64 cols
        float C2[64];
#pragma unroll
        for (int i = 0; i < 64; ++i) C2[i] = 0.f;

        // ---- 8 chunks of 32 hidden cols ----
#pragma unroll
        for (int c1 = 0; c1 < 8; ++c1) {
            // GEMM1 chunk: C1[(nt*2 + m)*4 + r], nt 0..3 within chunk
            float C1[32];
#pragma unroll
            for (int i = 0; i < 32; ++i) C1[i] = 0.f;
#pragma unroll
            for (int s = 0; s < 8; ++s) {
#pragma unroll
                for (int j = 0; j < 2; ++j) {
                    uint4 wv = w1s[(s * 16 + c1 * 2 + j) * 32 + lane];
#pragma unroll
                    for (int m = 0; m < 2; ++m) {
                        mma16816(C1 + ((2 * j + 0) * 2 + m) * 4, Ah[s] + 4 * m, wv.x, wv.y);
                        mma16816(C1 + ((2 * j + 1) * 2 + m) * 4, Ah[s] + 4 * m, wv.z, wv.w);
                    }
                }
            }

            // ---- epilogue + GEMM2 partial: 2 ksteps (q) per chunk ----
#pragma unroll
            for (int q = 0; q < 2; ++q) {
                uint32_t A2[2][4];
#pragma unroll
                for (int m = 0; m < 2; ++m) {
#pragma unroll
                    for (int h = 0; h < 2; ++h) {
                        const int nt = 2 * q + h;
                        const int col = c1 * 32 + nt * 8 + 2 * tig;
                        float2 ua = *(const float2*)(ub[2 * m]     + col);
                        float2 ubv = *(const float2*)(ub[2 * m + 1] + col);
                        const float* cp = C1 + (nt * 2 + m) * 4;
                        float f0 = fmaxf(cp[0] + ua.x,  0.f);
                        float f1 = fmaxf(cp[1] + ua.y,  0.f);
                        float f2 = fmaxf(cp[2] + ubv.x, 0.f);
                        float f3 = fmaxf(cp[3] + ubv.y, 0.f);
                        A2[m][2 * h + 0] = packf16(f0, f1);
                        A2[m][2 * h + 1] = packf16(f2, f3);
                    }
                }
#pragma unroll
                for (int ntp = 0; ntp < 4; ++ntp) {
                    uint4 wv = w2s[((c1 * 2 + q) * 4 + ntp) * 32 + lane];
#pragma unroll
                    for (int m = 0; m < 2; ++m) {
                        mma16816(C2 + ((2 * ntp + 0) * 2 + m) * 4, A2[m], wv.x, wv.y);
                        mma16816(C2 + ((2 * ntp + 1) * 2 + m) * 4, A2[m], wv.z, wv.w);
                    }
                }
            }
        }

        // ---- store out = C2 + b2 ----
#pragma unroll
        for (int nt2 = 0; nt2 < 8; ++nt2) {
            const int col = nt2 * 8 + 2 * tig;
            const float bx = b2s[col], by = b2s[col + 1];
#pragma unroll
            for (int m = 0; m < 2; ++m) {
                const float* cp = C2 + (nt2 * 2 + m) * 4;
                if (vv[2 * m]) {
                    float2 o; o.x = cp[0] + bx; o.y = cp[1] + by;
                    *(float2*)(out + ee[2 * m] * 64 + col) = o;
                }
                if (vv[2 * m + 1]) {
                    float2 o; o.x = cp[2] + bx; o.y = cp[3] + by;
                    *(float2*)(out + ee[2 * m + 1] * 64 + col) = o;
                }
            }
        }
    }
}

extern "C" void kernel_launch(void* const* d_in, const int* in_sizes, int n_in,
                              void* d_out, int out_size) {
    const float* src   = (const float*)d_in[0];
    const float* dest  = (const float*)d_in[1];
    /* d_in[2] = edge_attr, unused by the reference */
    const float* u     = (const float*)d_in[3];
    const int*   batch = (const int*)d_in[4];
    const float* W1    = (const float*)d_in[5];
    const float* b1    = (const float*)d_in[6];
    const float* W2    = (const float*)d_in[7];
    const float* b2    = (const float*)d_in[8];
    float* out = (float*)d_out;

    int E = in_sizes[4];
    int B = in_sizes[3] / FXD;

    ubb_kernel<<<B, 256>>>(u, W1, b1);

    int nsm = 148;
    cudaDeviceGetAttribute(&nsm, cudaDevAttrMultiProcessorCount, 0);
    long ngroups = ((long)E + 31) >> 5;
    long maxcta  = (ngroups + NW - 1) / NW;
    int grid = (int)(maxcta < (long)nsm ? maxcta : (long)nsm);

    cudaFuncSetAttribute(edge_mlp_hmma,
                         cudaFuncAttributeMaxDynamicSharedMemorySize, SMEM_SZ);
    edge_mlp_hmma<<<grid, NTHR, SMEM_SZ>>>(src, dest, batch, W1, W2, b2, out, E, B);
}